// round 14
// baseline (speedup 1.0000x reference)
#include <cuda_runtime.h>

#define NQ 12
#define NL 6
#define NG 72          // NL*NQ
#define DIM 4096
#define DIN 512
#define THREADS 64
#define KREG 64        // amps per thread
#define NPACK 32       // f32x2 packs per thread (pack bit = qubit 6)
#define MINBLOCKS 11   // 148*11=1628 blocks/wave -> 8192/1628 = 5.03 waves (kills tail)

// ---------------------------------------------------------------------------
// Compile-time circuit structure (same algebra as R6-R13, all passing):
//   RY(l,w): pair (i, i^mask), mask = col w of A^-l
//   sign(i) = +1 if parity(i & sel)=1 else -1, sel = row w of A^l
// Tan-lifting: a(i) += sign(i)*tan(h)*a(i^mask); the uniform cos(h) factors are
// deferred and (prod cos)^2 is folded into the measurement coefficients.
// Measurement <Z_w> uses sel = row w of A^6.
// Gate order within a layer is free (commuting RYs); we interleave crossing
// and register gates.
// ---------------------------------------------------------------------------
struct Circ {
    unsigned mask[NG];
    unsigned sel[NG];
    unsigned msel[NQ];
};

__host__ __device__ constexpr Circ make_circ() {
    Circ c{};
    unsigned Ap[NQ] = {}, Aip[NQ] = {};
    for (int i = 0; i < NQ; i++) { Ap[i] = 1u << i; Aip[i] = 1u << i; }
    for (int l = 0; l < NL; l++) {
        for (int w = 0; w < NQ; w++) {
            c.sel[l * NQ + w] = Ap[w];
            unsigned m = 0;
            for (int i = 0; i < NQ; i++) m |= ((Aip[i] >> w) & 1u) << i;
            c.mask[l * NQ + w] = m;
        }
        unsigned a = 0;
        for (int i = 0; i < NQ; i++) { a ^= Ap[i]; Ap[i] = a; }
        for (int i = NQ - 1; i >= 1; i--) Aip[i] ^= Aip[i - 1];
    }
    for (int w = 0; w < NQ; w++) c.msel[w] = Ap[w];
    return c;
}
constexpr Circ CC = make_circ();

// execution order: per layer interleave crossing and register gates
__host__ __device__ constexpr int gate_at(int P) {
    const int l = P / NQ, pos = P % NQ;
    const int w = (pos & 1) ? (6 + pos / 2) : (pos / 2);
    return l * NQ + w;
}

__host__ __device__ constexpr int popc_ct(unsigned x) {
    int n = 0; while (x) { n += x & 1u; x >>= 1; } return n;
}
__host__ __device__ constexpr unsigned topbit(unsigned x) {
    unsigned r = 0;
    for (int b = 31; b >= 0; b--) if ((x >> b) & 1u) { r = 1u << b; break; }
    return r;
}
constexpr bool check_circ() {
    for (int g = 0; g < NG; g++)
        if ((popc_ct(CC.mask[g] & CC.sel[g]) & 1) != 1) return false;
    for (int g = 0; g < NG; g++)
        if ((CC.mask[g] & 1u) && (CC.mask[g] >> 6)) return false;
    bool seen[NG] = {};
    for (int p = 0; p < NG; p++) {
        int g = gate_at(p);
        if (g < 0 || g >= NG || seen[g]) return false;
        seen[g] = true;
    }
    for (int p = 0; p < NG; p++)
        if (gate_at(p) / NQ != p / NQ) return false;
    return true;
}
static_assert(check_circ(), "circuit structure invariant violated");

// ---------------------------------------------------------------------------
// Packed f32x2 helpers (FFMA2 only reachable via PTX)
// ---------------------------------------------------------------------------
typedef unsigned long long u64;

__device__ __forceinline__ u64 pk2(float lo, float hi) {
    u64 r; asm("mov.b64 %0, {%1, %2};" : "=l"(r) : "f"(lo), "f"(hi)); return r;
}
__device__ __forceinline__ void upk2(u64 v, float& lo, float& hi) {
    asm("mov.b64 {%0, %1}, %2;" : "=f"(lo), "=f"(hi) : "l"(v));
}
__device__ __forceinline__ u64 swap2(u64 v) {
    float lo, hi; upk2(v, lo, hi); return pk2(hi, lo);
}
__device__ __forceinline__ u64 fma2(u64 a, u64 b, u64 c) {
    u64 d; asm("fma.rn.f32x2 %0, %1, %2, %3;" : "=l"(d) : "l"(a), "l"(b), "l"(c)); return d;
}
__device__ __forceinline__ u64 shflx2(u64 v, int m) {
    return __shfl_xor_sync(0xffffffffu, v, m);
}

// ---------------------------------------------------------------------------
// Layout: physical index i = (k<<6) | tl6, tl6 = thread-part (6 bits):
//   i bit 0      -> warp bit   (tid>>5)
//   i bits 1..5  -> lane bits  (tid&31)
//   i bits 6..11 -> per-thread k;  k bit 0 = f32x2 component, k bits 1..5 = pack j
// ---------------------------------------------------------------------------

struct SmemT {
    u64 buf[NPACK * THREADS];   // 16 KB state buffer for cross-warp gates
    float gt[NG];               // tan(h) per gate
    float vv0[NQ], vv1[NQ];
    float wsum[2][NQ];
    float postw[NQ];
    float red[2];
    float cred[2];              // per-warp partial products of cos
};

template<int G>
__device__ __forceinline__ void apply_gate(u64 A[NPACK], SmemT* sm, int tid, int tl6) {
    constexpr Circ CCk = make_circ();
    constexpr unsigned m    = CCk.mask[G];
    constexpr unsigned sl   = CCk.sel[G];
    constexpr unsigned mk   = m >> 6;          // k-space mask
    constexpr unsigned ml   = (m >> 1) & 31u;  // lane-space mask
    constexpr unsigned mw   = m & 1u;          // warp bit
    constexpr unsigned mkp  = mk >> 1;         // pack-index part of mask
    constexpr unsigned mb6  = mk & 1u;         // component-swap flag
    constexpr unsigned slk  = sl >> 6;
    constexpr unsigned slt  = sl & 63u;        // thread-part of sel
    constexpr unsigned slkp = slk >> 1;        // pack-index part of sel
    constexpr unsigned slc  = slk & 1u;        // component bit of sel

    const float t = sm->gt[G];
    const int pt = __popc((unsigned)tl6 & slt) & 1;
    const float sp = pt ? t : -t;
    const float f1 = slc ? -sp : sp;
    const u64 FP = pk2(sp, f1);
    const u64 FN = pk2(-sp, -f1);
    // fsvec(j) = parity(j & slkp) ? FN : FP

    if constexpr (mw == 0 && ml == 0) {
        // ---- register-local lifting butterfly ----
        if constexpr (mkp == 0) {
            static_assert(mb6 == 1, "empty register mask");
#pragma unroll
            for (int j = 0; j < NPACK; j++) {
                const u64 fs = (popc_ct((unsigned)j & slkp) & 1) ? FN : FP;
                A[j] = fma2(fs, swap2(A[j]), A[j]);
            }
        } else {
            constexpr unsigned hbp = topbit(mkp);
#pragma unroll
            for (int j0 = 0; j0 < NPACK; j0++) {
                if ((j0 & (int)hbp) == 0) {
                    const int j1 = j0 ^ (int)mkp;
                    const u64 fs0 = (popc_ct((unsigned)j0 & slkp) & 1) ? FN : FP;
                    const u64 fs1 = (popc_ct((unsigned)j1 & slkp) & 1) ? FN : FP;
                    u64 p0 = A[j1], p1 = A[j0];
                    if constexpr (mb6) { p0 = swap2(p0); p1 = swap2(p1); }
                    const u64 n0 = fma2(fs0, p0, A[j0]);
                    const u64 n1 = fma2(fs1, p1, A[j1]);
                    A[j0] = n0; A[j1] = n1;
                }
            }
        }
    } else if constexpr (mw == 0) {
        // ---- shuffle lifting (lane exchange) ----
        if constexpr (mkp == 0) {
#pragma unroll
            for (int j = 0; j < NPACK; j++) {
                u64 v = shflx2(A[j], (int)ml);
                if constexpr (mb6) v = swap2(v);
                const u64 fs = (popc_ct((unsigned)j & slkp) & 1) ? FN : FP;
                A[j] = fma2(fs, v, A[j]);
            }
        } else {
            constexpr unsigned hbp = topbit(mkp);
#pragma unroll
            for (int j0 = 0; j0 < NPACK; j0++) {
                if ((j0 & (int)hbp) == 0) {
                    const int j1 = j0 ^ (int)mkp;
                    u64 v1 = shflx2(A[j1], (int)ml);
                    u64 v0 = shflx2(A[j0], (int)ml);
                    if constexpr (mb6) { v1 = swap2(v1); v0 = swap2(v0); }
                    const u64 fs0 = (popc_ct((unsigned)j0 & slkp) & 1) ? FN : FP;
                    const u64 fs1 = (popc_ct((unsigned)j1 & slkp) & 1) ? FN : FP;
                    A[j0] = fma2(fs0, v1, A[j0]);
                    A[j1] = fma2(fs1, v0, A[j1]);
                }
            }
        }
    } else {
        // ---- cross-warp lifting via shared (mask has no k-space bits) ----
        static_assert(mk == 0, "shared gate with register mask bits");
        constexpr unsigned TMSK = (mw << 5) | ml;   // tid-space xor
#pragma unroll
        for (int j = 0; j < NPACK; j++) sm->buf[j * THREADS + tid] = A[j];
        __syncthreads();
        const u64* src = sm->buf + (tid ^ (int)TMSK);
#pragma unroll
        for (int j = 0; j < NPACK; j++) {
            const u64 v = src[j * THREADS];
            const u64 fs = (popc_ct((unsigned)j & slkp) & 1) ? FN : FP;
            A[j] = fma2(fs, v, A[j]);
        }
        __syncthreads();
    }
}

template<int P>
__device__ __forceinline__ void run_gates(u64 A[NPACK], SmemT* sm, int tid, int tl6) {
    if constexpr (P < NG) {
        apply_gate<gate_at(P)>(A, sm, tid, tl6);
        run_gates<P + 1>(A, sm, tid, tl6);
    }
}

// measurement helpers
template<int W>
__device__ __forceinline__ float msign_thread(int tl6, float pw) {
    constexpr Circ CCk = make_circ();
    constexpr unsigned mlo = CCk.msel[W] & 63u;
    return (__popc((unsigned)tl6 & mlo) & 1) ? -pw : pw;
}
template<int K, int W>
__device__ __forceinline__ constexpr float msign_k() {
    constexpr Circ CCk = make_circ();
    return (popc_ct((unsigned)K & (CCk.msel[W] >> 6)) & 1) ? -1.0f : 1.0f;
}
template<int K, int W>
__device__ __forceinline__ void meas_acc(float& cf, const float h[NQ]) {
    if constexpr (W < NQ) {
        cf += msign_k<K, W>() * h[W];
        meas_acc<K, W + 1>(cf, h);
    }
}
template<int J>
__device__ __forceinline__ void meas_packs(float& z, const u64 A[NPACK], const float h[NQ]) {
    if constexpr (J < NPACK) {
        float a0, a1;
        upk2(A[J], a0, a1);
        float cf0 = 0.0f, cf1 = 0.0f;
        meas_acc<2 * J, 0>(cf0, h);
        meas_acc<2 * J + 1, 0>(cf1, h);
        z = fmaf(a0 * a0, cf0, z);
        z = fmaf(a1 * a1, cf1, z);
        meas_packs<J + 1>(z, A, h);
    }
}
template<int W>
__device__ __forceinline__ void meas_h(float h[NQ], int tl6, const float* postw, float s2) {
    if constexpr (W < NQ) {
        h[W] = msign_thread<W>(tl6, postw[W] * s2);
        meas_h<W + 1>(h, tl6, postw, s2);
    }
}

__global__ __launch_bounds__(THREADS, MINBLOCKS) void dqc_kernel(
    const float* __restrict__ x,
    const float* __restrict__ pre_w,
    const float* __restrict__ pre_b,
    const float* __restrict__ weights,
    const float* __restrict__ post_w,
    const float* __restrict__ post_b,
    float* __restrict__ out)
{
    __shared__ SmemT sm;

    const int tid  = threadIdx.x;
    const int b    = blockIdx.x;
    const int lane = tid & 31;
    const int warp = tid >> 5;
    const int tl6 = warp | (lane << 1);   // thread-part of physical index

    // ---------------- pre-layer: 12 dot products of length 512 ----------------
    {
        const float4* xr = (const float4*)(x + (size_t)b * DIN);
        const float4 xa = xr[tid * 2];
        const float4 xb = xr[tid * 2 + 1];
        float acc[NQ];
#pragma unroll
        for (int w = 0; w < NQ; w++) {
            const float4* pr = (const float4*)(pre_w + w * DIN);
            const float4 pa = pr[tid * 2];
            const float4 pb = pr[tid * 2 + 1];
            float d = xa.x * pa.x + xa.y * pa.y + xa.z * pa.z + xa.w * pa.w;
            d += xb.x * pb.x + xb.y * pb.y + xb.z * pb.z + xb.w * pb.w;
            acc[w] = d;
        }
#pragma unroll
        for (int o = 16; o; o >>= 1)
#pragma unroll
            for (int w = 0; w < NQ; w++)
                acc[w] += __shfl_xor_sync(0xffffffffu, acc[w], o);
        if (lane == 0) {
#pragma unroll
            for (int w = 0; w < NQ; w++) sm.wsum[warp][w] = acc[w];
        }
    }
    __syncthreads();

    // ---------------- angles + gate tan + cos product ----------------
    if (tid < NQ) {
        float s = pre_b[tid] + sm.wsum[0][tid] + sm.wsum[1][tid];
        float h = s * 0.78539816339744830962f;   // pre * (pi/2) / 2
        float c, sn;
        sincosf(h, &sn, &c);
        const float is2 = 0.70710678118654752440f;
        sm.vv0[tid] = (c - sn) * is2;
        sm.vv1[tid] = (c + sn) * is2;
        sm.postw[tid] = post_w[tid];
    }
    {
        float cp = 1.0f;
        int g = tid;                       // gates 0..63
        float h = 0.5f * weights[g];
        float c, sn;
        sincosf(h, &sn, &c);
        sm.gt[g] = sn / c;
        cp = c;
        if (tid < NG - THREADS) {          // gates 64..71
            g = tid + THREADS;
            h = 0.5f * weights[g];
            sincosf(h, &sn, &c);
            sm.gt[g] = sn / c;
            cp *= c;
        }
#pragma unroll
        for (int o = 16; o; o >>= 1) cp *= __shfl_xor_sync(0xffffffffu, cp, o);
        if (lane == 0) sm.cred[warp] = cp;
    }
    __syncthreads();

    // ---------------- product-state init into packed registers ----------------
    u64 A[NPACK];
    {
        float base = 1.0f;
#pragma unroll
        for (int q = 0; q < 6; q++)
            base *= ((tl6 >> q) & 1) ? sm.vv1[q] : sm.vv0[q];
        float p67[4], p89[4], pAB[4];
#pragma unroll
        for (int j = 0; j < 4; j++) {
            p67[j] = ((j & 1) ? sm.vv1[6]  : sm.vv0[6])  * ((j & 2) ? sm.vv1[7]  : sm.vv0[7]);
            p89[j] = ((j & 1) ? sm.vv1[8]  : sm.vv0[8])  * ((j & 2) ? sm.vv1[9]  : sm.vv0[9]);
            pAB[j] = ((j & 1) ? sm.vv1[10] : sm.vv0[10]) * ((j & 2) ? sm.vv1[11] : sm.vv0[11]);
        }
#pragma unroll
        for (int j = 0; j < NPACK; j++) {
            const int k0 = 2 * j, k1 = 2 * j + 1;
            const float rest = p89[(j >> 1) & 3] * pAB[(j >> 3) & 3];
            const float a0 = (base * p67[k0 & 3]) * rest;
            const float a1 = (base * p67[k1 & 3]) * rest;
            A[j] = pk2(a0, a1);
        }
    }

    // ---------------- 72 lifting gates, interleaved order ----------------
    run_gates<0>(A, &sm, tid, tl6);

    // ---------------- measurement fused with post layer + deferred scale ------
    const float pc = sm.cred[0] * sm.cred[1];   // prod of cos over all gates
    const float s2 = pc * pc;                   // applies quadratically to probs
    float h[NQ];
    meas_h<0>(h, tl6, sm.postw, s2);
    float z = 0.0f;
    meas_packs<0>(z, A, h);
#pragma unroll
    for (int o = 16; o; o >>= 1) z += __shfl_xor_sync(0xffffffffu, z, o);
    if (lane == 0) sm.red[warp] = z;
    __syncthreads();
    if (tid == 0) {
        out[b] = post_b[0] + sm.red[0] + sm.red[1];
    }
}

extern "C" void kernel_launch(void* const* d_in, const int* in_sizes, int n_in,
                              void* d_out, int out_size) {
    const float* x       = (const float*)d_in[0];
    const float* pre_w   = (const float*)d_in[1];
    const float* pre_b   = (const float*)d_in[2];
    const float* weights = (const float*)d_in[3];
    const float* post_w  = (const float*)d_in[4];
    const float* post_b  = (const float*)d_in[5];
    float* out = (float*)d_out;

    int batch = in_sizes[0] / DIN;   // 8192
    dqc_kernel<<<batch, THREADS>>>(x, pre_w, pre_b, weights, post_w, post_b, out);
}

// round 15
// speedup vs baseline: 1.0732x; 1.0732x over previous
#include <cuda_runtime.h>

#define NQ 12
#define NL 6
#define NG 72          // NL*NQ
#define DIM 4096
#define DIN 512
#define THREADS 64
#define NPACK 32       // f32x2 packs per thread (pack bit = qubit 6)
#define MINBLOCKS 10   // known-good: 96 regs, no spill
#define BATCH_MAX 8192

// ---------------------------------------------------------------------------
// Compile-time circuit structure (same algebra as R6-R13, all passing):
//   RY(l,w): pair (i, i^mask), mask = col w of A^-l
//   sign(i) = +1 if parity(i & sel)=1 else -1, sel = row w of A^l
// Tan-lifting: a(i) += sign(i)*tan(h)*a(i^mask); deferred (prod cos)^2 folded
// into the measurement coefficients. Measurement <Z_w> uses sel = row w of A^6.
// Gate order within a layer is free (commuting RYs); interleaved order kept.
// ---------------------------------------------------------------------------
struct Circ {
    unsigned mask[NG];
    unsigned sel[NG];
    unsigned msel[NQ];
};

__host__ __device__ constexpr Circ make_circ() {
    Circ c{};
    unsigned Ap[NQ] = {}, Aip[NQ] = {};
    for (int i = 0; i < NQ; i++) { Ap[i] = 1u << i; Aip[i] = 1u << i; }
    for (int l = 0; l < NL; l++) {
        for (int w = 0; w < NQ; w++) {
            c.sel[l * NQ + w] = Ap[w];
            unsigned m = 0;
            for (int i = 0; i < NQ; i++) m |= ((Aip[i] >> w) & 1u) << i;
            c.mask[l * NQ + w] = m;
        }
        unsigned a = 0;
        for (int i = 0; i < NQ; i++) { a ^= Ap[i]; Ap[i] = a; }
        for (int i = NQ - 1; i >= 1; i--) Aip[i] ^= Aip[i - 1];
    }
    for (int w = 0; w < NQ; w++) c.msel[w] = Ap[w];
    return c;
}
constexpr Circ CC = make_circ();

// execution order: per layer interleave crossing and register gates
__host__ __device__ constexpr int gate_at(int P) {
    const int l = P / NQ, pos = P % NQ;
    const int w = (pos & 1) ? (6 + pos / 2) : (pos / 2);
    return l * NQ + w;
}

__host__ __device__ constexpr int popc_ct(unsigned x) {
    int n = 0; while (x) { n += x & 1u; x >>= 1; } return n;
}
__host__ __device__ constexpr unsigned topbit(unsigned x) {
    unsigned r = 0;
    for (int b = 31; b >= 0; b--) if ((x >> b) & 1u) { r = 1u << b; break; }
    return r;
}
constexpr bool check_circ() {
    for (int g = 0; g < NG; g++)
        if ((popc_ct(CC.mask[g] & CC.sel[g]) & 1) != 1) return false;
    for (int g = 0; g < NG; g++)
        if ((CC.mask[g] & 1u) && (CC.mask[g] >> 6)) return false;
    bool seen[NG] = {};
    for (int p = 0; p < NG; p++) {
        int g = gate_at(p);
        if (g < 0 || g >= NG || seen[g]) return false;
        seen[g] = true;
    }
    for (int p = 0; p < NG; p++)
        if (gate_at(p) / NQ != p / NQ) return false;
    return true;
}
static_assert(check_circ(), "circuit structure invariant violated");

// ---------------------------------------------------------------------------
// Device-global scratch (precomputed by helper kernels; no allocation)
// ---------------------------------------------------------------------------
__device__ float g_vv[BATCH_MAX][2][NQ];  // per-element qubit init vectors
__device__ float g_gt[NG];                // tan(h) per gate (batch-independent)
__device__ float g_s2;                    // (prod cos)^2

// ---------------------------------------------------------------------------
// Packed f32x2 helpers (FFMA2 only reachable via PTX)
// ---------------------------------------------------------------------------
typedef unsigned long long u64;

__device__ __forceinline__ u64 pk2(float lo, float hi) {
    u64 r; asm("mov.b64 %0, {%1, %2};" : "=l"(r) : "f"(lo), "f"(hi)); return r;
}
__device__ __forceinline__ void upk2(u64 v, float& lo, float& hi) {
    asm("mov.b64 {%0, %1}, %2;" : "=f"(lo), "=f"(hi) : "l"(v));
}
__device__ __forceinline__ u64 swap2(u64 v) {
    float lo, hi; upk2(v, lo, hi); return pk2(hi, lo);
}
__device__ __forceinline__ u64 mul2(u64 a, u64 b) {
    u64 d; asm("mul.rn.f32x2 %0, %1, %2;" : "=l"(d) : "l"(a), "l"(b)); return d;
}
__device__ __forceinline__ u64 fma2(u64 a, u64 b, u64 c) {
    u64 d; asm("fma.rn.f32x2 %0, %1, %2, %3;" : "=l"(d) : "l"(a), "l"(b), "l"(c)); return d;
}
__device__ __forceinline__ u64 shflx2(u64 v, int m) {
    return __shfl_xor_sync(0xffffffffu, v, m);
}

// ---------------------------------------------------------------------------
// Pre-kernel 1: weights trig (batch-independent). One block, 128 threads.
// ---------------------------------------------------------------------------
__global__ void wtrig_kernel(const float* __restrict__ weights) {
    __shared__ float cred[4];
    const int t = threadIdx.x;
    const int lane = t & 31, warp = t >> 5;
    float cp = 1.0f;
    if (t < NG) {
        float hh = 0.5f * weights[t];
        float c, sn;
        sincosf(hh, &sn, &c);
        g_gt[t] = sn / c;
        cp = c;
    }
#pragma unroll
    for (int o = 16; o; o >>= 1) cp *= __shfl_xor_sync(0xffffffffu, cp, o);
    if (lane == 0) cred[warp] = cp;
    __syncthreads();
    if (t == 0) {
        float pc = cred[0] * cred[1] * cred[2] * cred[3];
        g_s2 = pc * pc;
    }
}

// ---------------------------------------------------------------------------
// Pre-kernel 2: angles. One warp per batch element (8 warps/block).
// ---------------------------------------------------------------------------
__global__ __launch_bounds__(256) void angles_kernel(
    const float* __restrict__ x,
    const float* __restrict__ pre_w,
    const float* __restrict__ pre_b)
{
    const int lane = threadIdx.x & 31;
    const int wid  = threadIdx.x >> 5;
    const int b    = blockIdx.x * 8 + wid;

    const float4* xr = (const float4*)(x + (size_t)b * DIN);
    float4 xv[4];
#pragma unroll
    for (int i = 0; i < 4; i++) xv[i] = xr[lane + 32 * i];
    float acc[NQ];
#pragma unroll
    for (int w = 0; w < NQ; w++) {
        const float4* pr = (const float4*)(pre_w + w * DIN);
        float d = 0.0f;
#pragma unroll
        for (int i = 0; i < 4; i++) {
            const float4 pv = pr[lane + 32 * i];
            d += xv[i].x * pv.x + xv[i].y * pv.y + xv[i].z * pv.z + xv[i].w * pv.w;
        }
        acc[w] = d;
    }
#pragma unroll
    for (int o = 16; o; o >>= 1)
#pragma unroll
        for (int w = 0; w < NQ; w++)
            acc[w] += __shfl_xor_sync(0xffffffffu, acc[w], o);
    if (lane < NQ) {
        float s = pre_b[lane] + acc[lane];
        float hh = s * 0.78539816339744830962f;   // pre * (pi/2) / 2
        float c, sn;
        sincosf(hh, &sn, &c);
        const float is2 = 0.70710678118654752440f;
        g_vv[b][0][lane] = (c - sn) * is2;
        g_vv[b][1][lane] = (c + sn) * is2;
    }
}

// ---------------------------------------------------------------------------
// Main kernel. Layout: physical index i = (k<<6) | tl6:
//   i bit 0 -> warp bit (tid>>5); i bits 1..5 -> lane bits (tid&31)
//   i bits 6..11 -> per-thread k; k bit 0 = f32x2 component, k bits 1..5 = pack j
// ---------------------------------------------------------------------------

struct SmemT {
    u64 buf[NPACK * THREADS];   // 16 KB state buffer for cross-warp gates
    float gt[NG];
    float vv[2][NQ];
    float postw[NQ];            // post_w * (prod cos)^2
    float red[2];
};

template<int G>
__device__ __forceinline__ void apply_gate(u64 A[NPACK], SmemT* sm, int tid, int tl6) {
    constexpr Circ CCk = make_circ();
    constexpr unsigned m    = CCk.mask[G];
    constexpr unsigned sl   = CCk.sel[G];
    constexpr unsigned mk   = m >> 6;          // k-space mask
    constexpr unsigned ml   = (m >> 1) & 31u;  // lane-space mask
    constexpr unsigned mw   = m & 1u;          // warp bit
    constexpr unsigned mkp  = mk >> 1;         // pack-index part of mask
    constexpr unsigned mb6  = mk & 1u;         // component-swap flag
    constexpr unsigned slk  = sl >> 6;
    constexpr unsigned slt  = sl & 63u;        // thread-part of sel
    constexpr unsigned slkp = slk >> 1;        // pack-index part of sel
    constexpr unsigned slc  = slk & 1u;        // component bit of sel

    const float t = sm->gt[G];
    const int pt = __popc((unsigned)tl6 & slt) & 1;
    const float sp = pt ? t : -t;
    const float f1 = slc ? -sp : sp;
    const u64 FP = pk2(sp, f1);
    const u64 FN = pk2(-sp, -f1);
    // fsvec(j) = parity(j & slkp) ? FN : FP

    if constexpr (mw == 0 && ml == 0) {
        // ---- register-local lifting butterfly ----
        if constexpr (mkp == 0) {
            static_assert(mb6 == 1, "empty register mask");
#pragma unroll
            for (int j = 0; j < NPACK; j++) {
                const u64 fs = (popc_ct((unsigned)j & slkp) & 1) ? FN : FP;
                A[j] = fma2(fs, swap2(A[j]), A[j]);
            }
        } else {
            constexpr unsigned hbp = topbit(mkp);
#pragma unroll
            for (int j0 = 0; j0 < NPACK; j0++) {
                if ((j0 & (int)hbp) == 0) {
                    const int j1 = j0 ^ (int)mkp;
                    const u64 fs0 = (popc_ct((unsigned)j0 & slkp) & 1) ? FN : FP;
                    const u64 fs1 = (popc_ct((unsigned)j1 & slkp) & 1) ? FN : FP;
                    u64 p0 = A[j1], p1 = A[j0];
                    if constexpr (mb6) { p0 = swap2(p0); p1 = swap2(p1); }
                    const u64 n0 = fma2(fs0, p0, A[j0]);
                    const u64 n1 = fma2(fs1, p1, A[j1]);
                    A[j0] = n0; A[j1] = n1;
                }
            }
        }
    } else if constexpr (mw == 0) {
        // ---- shuffle lifting (lane exchange) ----
        if constexpr (mkp == 0) {
#pragma unroll
            for (int j = 0; j < NPACK; j++) {
                u64 v = shflx2(A[j], (int)ml);
                if constexpr (mb6) v = swap2(v);
                const u64 fs = (popc_ct((unsigned)j & slkp) & 1) ? FN : FP;
                A[j] = fma2(fs, v, A[j]);
            }
        } else {
            constexpr unsigned hbp = topbit(mkp);
#pragma unroll
            for (int j0 = 0; j0 < NPACK; j0++) {
                if ((j0 & (int)hbp) == 0) {
                    const int j1 = j0 ^ (int)mkp;
                    u64 v1 = shflx2(A[j1], (int)ml);
                    u64 v0 = shflx2(A[j0], (int)ml);
                    if constexpr (mb6) { v1 = swap2(v1); v0 = swap2(v0); }
                    const u64 fs0 = (popc_ct((unsigned)j0 & slkp) & 1) ? FN : FP;
                    const u64 fs1 = (popc_ct((unsigned)j1 & slkp) & 1) ? FN : FP;
                    A[j0] = fma2(fs0, v1, A[j0]);
                    A[j1] = fma2(fs1, v0, A[j1]);
                }
            }
        }
    } else {
        // ---- cross-warp lifting via shared (mask has no k-space bits) ----
        static_assert(mk == 0, "shared gate with register mask bits");
        constexpr unsigned TMSK = (mw << 5) | ml;   // tid-space xor
#pragma unroll
        for (int j = 0; j < NPACK; j++) sm->buf[j * THREADS + tid] = A[j];
        __syncthreads();
        const u64* src = sm->buf + (tid ^ (int)TMSK);
#pragma unroll
        for (int j = 0; j < NPACK; j++) {
            const u64 v = src[j * THREADS];
            const u64 fs = (popc_ct((unsigned)j & slkp) & 1) ? FN : FP;
            A[j] = fma2(fs, v, A[j]);
        }
        __syncthreads();
    }
}

template<int P>
__device__ __forceinline__ void run_gates(u64 A[NPACK], SmemT* sm, int tid, int tl6) {
    if constexpr (P < NG) {
        apply_gate<gate_at(P)>(A, sm, tid, tl6);
        run_gates<P + 1>(A, sm, tid, tl6);
    }
}

// ---- packed measurement ----
// sign(i,w) = parity(tl6 & msel_lo6) ^ parity(comp & msel_bit6) ^ parity(j & msel>>7)
template<int W>
__device__ __forceinline__ void meas_hp(u64 Hp[NQ], int tl6, const float* postw) {
    if constexpr (W < NQ) {
        constexpr Circ CCk = make_circ();
        constexpr unsigned mlo = CCk.msel[W] & 63u;
        constexpr unsigned mb6 = (CCk.msel[W] >> 6) & 1u;
        const float h0 = (__popc((unsigned)tl6 & mlo) & 1) ? -postw[W] : postw[W];
        const float h1 = mb6 ? -h0 : h0;
        Hp[W] = pk2(h0, h1);
        meas_hp<W + 1>(Hp, tl6, postw);
    }
}
template<int J, int W>
__device__ __forceinline__ void meas_cf(u64& cf, const u64 Hp[NQ], u64 P1, u64 M1) {
    if constexpr (W < NQ) {
        constexpr Circ CCk = make_circ();
        constexpr bool neg = (popc_ct((unsigned)J & (CCk.msel[W] >> 7)) & 1) != 0;
        cf = fma2(Hp[W], neg ? M1 : P1, cf);
        meas_cf<J, W + 1>(cf, Hp, P1, M1);
    }
}
template<int J>
__device__ __forceinline__ void meas_packs(u64& z2, const u64 A[NPACK], const u64 Hp[NQ],
                                           u64 P1, u64 M1, u64 Z0) {
    if constexpr (J < NPACK) {
        u64 cf = Z0;
        meas_cf<J, 0>(cf, Hp, P1, M1);
        z2 = fma2(mul2(A[J], A[J]), cf, z2);
        meas_packs<J + 1>(z2, A, Hp, P1, M1, Z0);
    }
}

__global__ __launch_bounds__(THREADS, MINBLOCKS) void dqc_kernel(
    const float* __restrict__ post_w,
    const float* __restrict__ post_b,
    float* __restrict__ out)
{
    __shared__ SmemT sm;

    const int tid  = threadIdx.x;
    const int b    = blockIdx.x;
    const int lane = tid & 31;
    const int warp = tid >> 5;
    const int tl6 = warp | (lane << 1);   // thread-part of physical index

    // ---------------- tiny head: load precomputed scalars ----------------
    if (tid < 24) ((float*)sm.vv)[tid] = ((const float*)g_vv[b])[tid];
    sm.gt[tid] = g_gt[tid];
    if (tid < NG - THREADS) sm.gt[THREADS + tid] = g_gt[THREADS + tid];
    if (tid < NQ) sm.postw[tid] = post_w[tid] * g_s2;
    __syncthreads();

    // ---------------- product-state init into packed registers ----------------
    u64 A[NPACK];
    {
        float base = 1.0f;
#pragma unroll
        for (int q = 0; q < 6; q++)
            base *= ((tl6 >> q) & 1) ? sm.vv[1][q] : sm.vv[0][q];
        float p67[4], p89[4], pAB[4];
#pragma unroll
        for (int j = 0; j < 4; j++) {
            p67[j] = ((j & 1) ? sm.vv[1][6]  : sm.vv[0][6])  * ((j & 2) ? sm.vv[1][7]  : sm.vv[0][7]);
            p89[j] = ((j & 1) ? sm.vv[1][8]  : sm.vv[0][8])  * ((j & 2) ? sm.vv[1][9]  : sm.vv[0][9]);
            pAB[j] = ((j & 1) ? sm.vv[1][10] : sm.vv[0][10]) * ((j & 2) ? sm.vv[1][11] : sm.vv[0][11]);
        }
#pragma unroll
        for (int j = 0; j < NPACK; j++) {
            const int k0 = 2 * j, k1 = 2 * j + 1;
            const float rest = p89[(j >> 1) & 3] * pAB[(j >> 3) & 3];
            const float a0 = (base * p67[k0 & 3]) * rest;
            const float a1 = (base * p67[k1 & 3]) * rest;
            A[j] = pk2(a0, a1);
        }
    }

    // ---------------- 72 lifting gates, interleaved order ----------------
    run_gates<0>(A, &sm, tid, tl6);

    // ---------------- packed measurement fused with post layer ----------------
    u64 Hp[NQ];
    meas_hp<0>(Hp, tl6, sm.postw);
    const u64 P1 = pk2(1.0f, 1.0f);
    const u64 M1 = pk2(-1.0f, -1.0f);
    const u64 Z0 = pk2(0.0f, 0.0f);
    u64 z2 = Z0;
    meas_packs<0>(z2, A, Hp, P1, M1, Z0);
    float z0, z1;
    upk2(z2, z0, z1);
    float z = z0 + z1;
#pragma unroll
    for (int o = 16; o; o >>= 1) z += __shfl_xor_sync(0xffffffffu, z, o);
    if (lane == 0) sm.red[warp] = z;
    __syncthreads();
    if (tid == 0) {
        out[b] = post_b[0] + sm.red[0] + sm.red[1];
    }
}

extern "C" void kernel_launch(void* const* d_in, const int* in_sizes, int n_in,
                              void* d_out, int out_size) {
    const float* x       = (const float*)d_in[0];
    const float* pre_w   = (const float*)d_in[1];
    const float* pre_b   = (const float*)d_in[2];
    const float* weights = (const float*)d_in[3];
    const float* post_w  = (const float*)d_in[4];
    const float* post_b  = (const float*)d_in[5];
    float* out = (float*)d_out;

    int batch = in_sizes[0] / DIN;   // 8192
    wtrig_kernel<<<1, 128>>>(weights);
    angles_kernel<<<batch / 8, 256>>>(x, pre_w, pre_b);
    dqc_kernel<<<batch, THREADS>>>(post_w, post_b, out);
}

// round 16
// speedup vs baseline: 1.0937x; 1.0191x over previous
#include <cuda_runtime.h>

#define NQ 12
#define NL 6
#define NG 72          // NL*NQ
#define DIM 4096
#define DIN 512
#define THREADS 64
#define NPACK 32       // f32x2 packs per thread (pack bit = qubit 6)
#define MINBLOCKS 10   // known-good: 96 regs, no spill; 5.54/6 waves
#define BATCH_MAX 8192

// ---------------------------------------------------------------------------
// Compile-time circuit structure (same algebra as R6-R15, all passing):
//   RY(l,w): pair (i, i^mask), mask = col w of A^-l
//   sign(i) = +1 if parity(i & sel)=1 else -1, sel = row w of A^l
// Tan-lifting: a(i) += sign(i)*tan(h)*a(i^mask); deferred (prod cos)^2 folded
// into the measurement coefficients. Measurement <Z_w> uses sel = row w of A^6.
// Gate order within a layer is free (commuting RYs); interleaved order kept.
// ---------------------------------------------------------------------------
struct Circ {
    unsigned mask[NG];
    unsigned sel[NG];
    unsigned msel[NQ];
};

__host__ __device__ constexpr Circ make_circ() {
    Circ c{};
    unsigned Ap[NQ] = {}, Aip[NQ] = {};
    for (int i = 0; i < NQ; i++) { Ap[i] = 1u << i; Aip[i] = 1u << i; }
    for (int l = 0; l < NL; l++) {
        for (int w = 0; w < NQ; w++) {
            c.sel[l * NQ + w] = Ap[w];
            unsigned m = 0;
            for (int i = 0; i < NQ; i++) m |= ((Aip[i] >> w) & 1u) << i;
            c.mask[l * NQ + w] = m;
        }
        unsigned a = 0;
        for (int i = 0; i < NQ; i++) { a ^= Ap[i]; Ap[i] = a; }
        for (int i = NQ - 1; i >= 1; i--) Aip[i] ^= Aip[i - 1];
    }
    for (int w = 0; w < NQ; w++) c.msel[w] = Ap[w];
    return c;
}
constexpr Circ CC = make_circ();

// execution order: per layer interleave crossing and register gates
__host__ __device__ constexpr int gate_at(int P) {
    const int l = P / NQ, pos = P % NQ;
    const int w = (pos & 1) ? (6 + pos / 2) : (pos / 2);
    return l * NQ + w;
}

__host__ __device__ constexpr int popc_ct(unsigned x) {
    int n = 0; while (x) { n += x & 1u; x >>= 1; } return n;
}
__host__ __device__ constexpr unsigned topbit(unsigned x) {
    unsigned r = 0;
    for (int b = 31; b >= 0; b--) if ((x >> b) & 1u) { r = 1u << b; break; }
    return r;
}
// is there a smem-class gate at execution position > P?
__host__ __device__ constexpr bool smem_gate_after(int P) {
    constexpr Circ c = make_circ();
    for (int p = P + 1; p < NG; p++)
        if ((c.mask[gate_at(p)] & 1u) != 0) return true;
    return false;
}
constexpr bool check_circ() {
    for (int g = 0; g < NG; g++)
        if ((popc_ct(CC.mask[g] & CC.sel[g]) & 1) != 1) return false;
    for (int g = 0; g < NG; g++)
        if ((CC.mask[g] & 1u) && (CC.mask[g] >> 6)) return false;
    bool seen[NG] = {};
    for (int p = 0; p < NG; p++) {
        int g = gate_at(p);
        if (g < 0 || g >= NG || seen[g]) return false;
        seen[g] = true;
    }
    for (int p = 0; p < NG; p++)
        if (gate_at(p) / NQ != p / NQ) return false;
    return true;
}
static_assert(check_circ(), "circuit structure invariant violated");

// ---------------------------------------------------------------------------
// Device-global scratch (precomputed by the angles kernel; no allocation)
// ---------------------------------------------------------------------------
__device__ float g_vv[BATCH_MAX][2][NQ];  // per-element qubit init vectors
__device__ float g_gt[NG];                // tan(h) per gate (batch-independent)
__device__ float g_s2;                    // (prod cos)^2

// ---------------------------------------------------------------------------
// Packed f32x2 helpers (FFMA2 only reachable via PTX)
// ---------------------------------------------------------------------------
typedef unsigned long long u64;

__device__ __forceinline__ u64 pk2(float lo, float hi) {
    u64 r; asm("mov.b64 %0, {%1, %2};" : "=l"(r) : "f"(lo), "f"(hi)); return r;
}
__device__ __forceinline__ void upk2(u64 v, float& lo, float& hi) {
    asm("mov.b64 {%0, %1}, %2;" : "=f"(lo), "=f"(hi) : "l"(v));
}
__device__ __forceinline__ u64 swap2(u64 v) {
    float lo, hi; upk2(v, lo, hi); return pk2(hi, lo);
}
__device__ __forceinline__ u64 mul2(u64 a, u64 b) {
    u64 d; asm("mul.rn.f32x2 %0, %1, %2;" : "=l"(d) : "l"(a), "l"(b)); return d;
}
__device__ __forceinline__ u64 fma2(u64 a, u64 b, u64 c) {
    u64 d; asm("fma.rn.f32x2 %0, %1, %2, %3;" : "=l"(d) : "l"(a), "l"(b), "l"(c)); return d;
}
__device__ __forceinline__ u64 shflx2(u64 v, int m) {
    return __shfl_xor_sync(0xffffffffu, v, m);
}

// ---------------------------------------------------------------------------
// Pre-kernel: angles (one warp per batch element, 8/block) + weights trig
// (warp 0 of block 0, 3 gates per lane, warp product-reduction, no barriers).
// ---------------------------------------------------------------------------
__global__ __launch_bounds__(256) void angles_kernel(
    const float* __restrict__ x,
    const float* __restrict__ pre_w,
    const float* __restrict__ pre_b,
    const float* __restrict__ weights)
{
    const int lane = threadIdx.x & 31;
    const int wid  = threadIdx.x >> 5;
    const int b    = blockIdx.x * 8 + wid;

    const float4* xr = (const float4*)(x + (size_t)b * DIN);
    float4 xv[4];
#pragma unroll
    for (int i = 0; i < 4; i++) xv[i] = xr[lane + 32 * i];
    float acc[NQ];
#pragma unroll
    for (int w = 0; w < NQ; w++) {
        const float4* pr = (const float4*)(pre_w + w * DIN);
        float d = 0.0f;
#pragma unroll
        for (int i = 0; i < 4; i++) {
            const float4 pv = pr[lane + 32 * i];
            d += xv[i].x * pv.x + xv[i].y * pv.y + xv[i].z * pv.z + xv[i].w * pv.w;
        }
        acc[w] = d;
    }
#pragma unroll
    for (int o = 16; o; o >>= 1)
#pragma unroll
        for (int w = 0; w < NQ; w++)
            acc[w] += __shfl_xor_sync(0xffffffffu, acc[w], o);
    if (lane < NQ) {
        float s = pre_b[lane] + acc[lane];
        float hh = s * 0.78539816339744830962f;   // pre * (pi/2) / 2
        float c, sn;
        sincosf(hh, &sn, &c);
        const float is2 = 0.70710678118654752440f;
        g_vv[b][0][lane] = (c - sn) * is2;
        g_vv[b][1][lane] = (c + sn) * is2;
    }

    // weights trig: block 0, warp 0 only (3 gates per lane, lanes 0..31)
    if (blockIdx.x == 0 && wid == 0) {
        float cp = 1.0f;
#pragma unroll
        for (int r = 0; r < 3; r++) {
            const int g = lane + 32 * r;
            if (g < NG) {
                float hh = 0.5f * weights[g];
                float c, sn;
                sincosf(hh, &sn, &c);
                g_gt[g] = sn / c;
                cp *= c;
            }
        }
#pragma unroll
        for (int o = 16; o; o >>= 1) cp *= __shfl_xor_sync(0xffffffffu, cp, o);
        if (lane == 0) g_s2 = cp * cp;
    }
}

// ---------------------------------------------------------------------------
// Main kernel. Layout: physical index i = (k<<6) | tl6:
//   i bit 0 -> warp bit (tid>>5); i bits 1..5 -> lane bits (tid&31)
//   i bits 6..11 -> per-thread k; k bit 0 = f32x2 component, k bits 1..5 = pack j
// ---------------------------------------------------------------------------

struct SmemT {
    u64 buf[NPACK * THREADS];   // 16 KB state buffer for cross-warp gates
    float gt[NG];
    float vv[2][NQ];
    float postw[NQ];            // post_w * (prod cos)^2
    float red[2];
};

template<int G, bool TRAIL_SYNC>
__device__ __forceinline__ void apply_gate(u64 A[NPACK], SmemT* sm, int tid, int tl6) {
    constexpr Circ CCk = make_circ();
    constexpr unsigned m    = CCk.mask[G];
    constexpr unsigned sl   = CCk.sel[G];
    constexpr unsigned mk   = m >> 6;          // k-space mask
    constexpr unsigned ml   = (m >> 1) & 31u;  // lane-space mask
    constexpr unsigned mw   = m & 1u;          // warp bit
    constexpr unsigned mkp  = mk >> 1;         // pack-index part of mask
    constexpr unsigned mb6  = mk & 1u;         // component-swap flag
    constexpr unsigned slk  = sl >> 6;
    constexpr unsigned slt  = sl & 63u;        // thread-part of sel
    constexpr unsigned slkp = slk >> 1;        // pack-index part of sel
    constexpr unsigned slc  = slk & 1u;        // component bit of sel

    const float t = sm->gt[G];
    const int pt = __popc((unsigned)tl6 & slt) & 1;
    const float sp = pt ? t : -t;
    const float f1 = slc ? -sp : sp;
    const u64 FP = pk2(sp, f1);
    const u64 FN = pk2(-sp, -f1);
    // fsvec(j) = parity(j & slkp) ? FN : FP

    if constexpr (mw == 0 && ml == 0) {
        // ---- register-local lifting butterfly ----
        if constexpr (mkp == 0) {
            static_assert(mb6 == 1, "empty register mask");
#pragma unroll
            for (int j = 0; j < NPACK; j++) {
                const u64 fs = (popc_ct((unsigned)j & slkp) & 1) ? FN : FP;
                A[j] = fma2(fs, swap2(A[j]), A[j]);
            }
        } else {
            constexpr unsigned hbp = topbit(mkp);
#pragma unroll
            for (int j0 = 0; j0 < NPACK; j0++) {
                if ((j0 & (int)hbp) == 0) {
                    const int j1 = j0 ^ (int)mkp;
                    const u64 fs0 = (popc_ct((unsigned)j0 & slkp) & 1) ? FN : FP;
                    const u64 fs1 = (popc_ct((unsigned)j1 & slkp) & 1) ? FN : FP;
                    u64 p0 = A[j1], p1 = A[j0];
                    if constexpr (mb6) { p0 = swap2(p0); p1 = swap2(p1); }
                    const u64 n0 = fma2(fs0, p0, A[j0]);
                    const u64 n1 = fma2(fs1, p1, A[j1]);
                    A[j0] = n0; A[j1] = n1;
                }
            }
        }
    } else if constexpr (mw == 0) {
        // ---- shuffle lifting (lane exchange) ----
        if constexpr (mkp == 0) {
#pragma unroll
            for (int j = 0; j < NPACK; j++) {
                u64 v = shflx2(A[j], (int)ml);
                if constexpr (mb6) v = swap2(v);
                const u64 fs = (popc_ct((unsigned)j & slkp) & 1) ? FN : FP;
                A[j] = fma2(fs, v, A[j]);
            }
        } else {
            constexpr unsigned hbp = topbit(mkp);
#pragma unroll
            for (int j0 = 0; j0 < NPACK; j0++) {
                if ((j0 & (int)hbp) == 0) {
                    const int j1 = j0 ^ (int)mkp;
                    u64 v1 = shflx2(A[j1], (int)ml);
                    u64 v0 = shflx2(A[j0], (int)ml);
                    if constexpr (mb6) { v1 = swap2(v1); v0 = swap2(v0); }
                    const u64 fs0 = (popc_ct((unsigned)j0 & slkp) & 1) ? FN : FP;
                    const u64 fs1 = (popc_ct((unsigned)j1 & slkp) & 1) ? FN : FP;
                    A[j0] = fma2(fs0, v1, A[j0]);
                    A[j1] = fma2(fs1, v0, A[j1]);
                }
            }
        }
    } else {
        // ---- cross-warp lifting via shared (mask has no k-space bits) ----
        static_assert(mk == 0, "shared gate with register mask bits");
        constexpr unsigned TMSK = (mw << 5) | ml;   // tid-space xor
#pragma unroll
        for (int j = 0; j < NPACK; j++) sm->buf[j * THREADS + tid] = A[j];
        __syncthreads();
        const u64* src = sm->buf + (tid ^ (int)TMSK);
#pragma unroll
        for (int j = 0; j < NPACK; j++) {
            const u64 v = src[j * THREADS];
            const u64 fs = (popc_ct((unsigned)j & slkp) & 1) ? FN : FP;
            A[j] = fma2(fs, v, A[j]);
        }
        if constexpr (TRAIL_SYNC) __syncthreads();  // protect buf reuse by the
                                                    // next smem gate (if any)
    }
}

template<int P>
__device__ __forceinline__ void run_gates(u64 A[NPACK], SmemT* sm, int tid, int tl6) {
    if constexpr (P < NG) {
        apply_gate<gate_at(P), smem_gate_after(P)>(A, sm, tid, tl6);
        run_gates<P + 1>(A, sm, tid, tl6);
    }
}

// ---- packed measurement ----
// sign(i,w) = parity(tl6 & msel_lo6) ^ parity(comp & msel_bit6) ^ parity(j & msel>>7)
template<int W>
__device__ __forceinline__ void meas_hp(u64 Hp[NQ], int tl6, const float* postw) {
    if constexpr (W < NQ) {
        constexpr Circ CCk = make_circ();
        constexpr unsigned mlo = CCk.msel[W] & 63u;
        constexpr unsigned mb6 = (CCk.msel[W] >> 6) & 1u;
        const float h0 = (__popc((unsigned)tl6 & mlo) & 1) ? -postw[W] : postw[W];
        const float h1 = mb6 ? -h0 : h0;
        Hp[W] = pk2(h0, h1);
        meas_hp<W + 1>(Hp, tl6, postw);
    }
}
template<int J, int W>
__device__ __forceinline__ void meas_cf(u64& cf, const u64 Hp[NQ], u64 P1, u64 M1) {
    if constexpr (W < NQ) {
        constexpr Circ CCk = make_circ();
        constexpr bool neg = (popc_ct((unsigned)J & (CCk.msel[W] >> 7)) & 1) != 0;
        cf = fma2(Hp[W], neg ? M1 : P1, cf);
        meas_cf<J, W + 1>(cf, Hp, P1, M1);
    }
}
template<int J>
__device__ __forceinline__ void meas_packs(u64& z2, const u64 A[NPACK], const u64 Hp[NQ],
                                           u64 P1, u64 M1, u64 Z0) {
    if constexpr (J < NPACK) {
        u64 cf = Z0;
        meas_cf<J, 0>(cf, Hp, P1, M1);
        z2 = fma2(mul2(A[J], A[J]), cf, z2);
        meas_packs<J + 1>(z2, A, Hp, P1, M1, Z0);
    }
}

__global__ __launch_bounds__(THREADS, MINBLOCKS) void dqc_kernel(
    const float* __restrict__ post_w,
    const float* __restrict__ post_b,
    float* __restrict__ out)
{
    __shared__ SmemT sm;

    const int tid  = threadIdx.x;
    const int b    = blockIdx.x;
    const int lane = tid & 31;
    const int warp = tid >> 5;
    const int tl6 = warp | (lane << 1);   // thread-part of physical index

    // ---------------- tiny head: load precomputed scalars ----------------
    if (tid < 24) ((float*)sm.vv)[tid] = ((const float*)g_vv[b])[tid];
    sm.gt[tid] = g_gt[tid];
    if (tid < NG - THREADS) sm.gt[THREADS + tid] = g_gt[THREADS + tid];
    if (tid < NQ) sm.postw[tid] = post_w[tid] * g_s2;
    __syncthreads();

    // ---------------- product-state init into packed registers ----------------
    u64 A[NPACK];
    {
        float base = 1.0f;
#pragma unroll
        for (int q = 0; q < 6; q++)
            base *= ((tl6 >> q) & 1) ? sm.vv[1][q] : sm.vv[0][q];
        float p67[4], p89[4], pAB[4];
#pragma unroll
        for (int j = 0; j < 4; j++) {
            p67[j] = ((j & 1) ? sm.vv[1][6]  : sm.vv[0][6])  * ((j & 2) ? sm.vv[1][7]  : sm.vv[0][7]);
            p89[j] = ((j & 1) ? sm.vv[1][8]  : sm.vv[0][8])  * ((j & 2) ? sm.vv[1][9]  : sm.vv[0][9]);
            pAB[j] = ((j & 1) ? sm.vv[1][10] : sm.vv[0][10]) * ((j & 2) ? sm.vv[1][11] : sm.vv[0][11]);
        }
#pragma unroll
        for (int j = 0; j < NPACK; j++) {
            const int k0 = 2 * j, k1 = 2 * j + 1;
            const float rest = p89[(j >> 1) & 3] * pAB[(j >> 3) & 3];
            const float a0 = (base * p67[k0 & 3]) * rest;
            const float a1 = (base * p67[k1 & 3]) * rest;
            A[j] = pk2(a0, a1);
        }
    }

    // ---------------- 72 lifting gates, interleaved order ----------------
    run_gates<0>(A, &sm, tid, tl6);

    // ---------------- packed measurement fused with post layer ----------------
    u64 Hp[NQ];
    meas_hp<0>(Hp, tl6, sm.postw);
    const u64 P1 = pk2(1.0f, 1.0f);
    const u64 M1 = pk2(-1.0f, -1.0f);
    const u64 Z0 = pk2(0.0f, 0.0f);
    u64 z2 = Z0;
    meas_packs<0>(z2, A, Hp, P1, M1, Z0);
    float z0, z1;
    upk2(z2, z0, z1);
    float z = z0 + z1;
#pragma unroll
    for (int o = 16; o; o >>= 1) z += __shfl_xor_sync(0xffffffffu, z, o);
    if (lane == 0) sm.red[warp] = z;
    __syncthreads();
    if (tid == 0) {
        out[b] = post_b[0] + sm.red[0] + sm.red[1];
    }
}

extern "C" void kernel_launch(void* const* d_in, const int* in_sizes, int n_in,
                              void* d_out, int out_size) {
    const float* x       = (const float*)d_in[0];
    const float* pre_w   = (const float*)d_in[1];
    const float* pre_b   = (const float*)d_in[2];
    const float* weights = (const float*)d_in[3];
    const float* post_w  = (const float*)d_in[4];
    const float* post_b  = (const float*)d_in[5];
    float* out = (float*)d_out;

    int batch = in_sizes[0] / DIN;   // 8192
    angles_kernel<<<batch / 8, 256>>>(x, pre_w, pre_b, weights);
    dqc_kernel<<<batch, THREADS>>>(post_w, post_b, out);
}